// round 7
// baseline (speedup 1.0000x reference)
#include <cuda_runtime.h>

// DTW 65536 x 512 — 4 CTAs x 128 threads, 1 column/lane, R=16 rows/tick.
// ac[r][j] = min(ac[r-1][j-1], ac[r-1][j], ac[r][j-1]) + (k[j]-x[r])^2
// Thread tid = column; tick t = i - 32*w - l; 16 rows per tick.
//   intra-warp  handoff: shfl_up (lane 0 overridden from mailbox/staging)
//   intra-CTA   handoff: 8-deep smem mailbox + acquire/release flags (NO bar)
//   cross-CTA   handoff: global edge arrays + gpu-scope acquire/release flags,
//                        staged by warp 0 into its private smem chunk buffer
// x is served from per-warp smem rings (80B slot stride -> conflict-free LDS).
//
// R7 = R6 with two tail-deadlock fixes:
//   (a) cross-CTA staging wait clamped to min(base+CHUNK, NTICK)
//   (b) mailbox consumer waits only while its own tick is in range

#define N_ROWS  65536
#define NCTA    4
#define NTHR    128
#define R       16
#define NTICK   (N_ROWS / R)          // 4096
#define NITER   (NTICK + NTHR - 1)    // 4223
#define CHUNK   32
#define MBD     8                     // mailbox depth (power of 2)
#define XSTRIDE 20                    // floats per ring slot (16 data + 4 pad)

__device__ __align__(16) float g_edge[NCTA - 1][N_ROWS];
__device__ int g_flag[NCTA - 1];

__global__ void dtw_init_flags()
{
    if (threadIdx.x < NCTA - 1) g_flag[threadIdx.x] = 0;
}

__device__ __forceinline__ int gflag_acquire(const int* p)
{
    int v;
    asm volatile("ld.acquire.gpu.global.b32 %0, [%1];" : "=r"(v) : "l"(p) : "memory");
    return v;
}
__device__ __forceinline__ void gflag_release(int* p, int v)
{
    asm volatile("st.release.gpu.global.b32 [%0], %1;" :: "l"(p), "r"(v) : "memory");
}
__device__ __forceinline__ int sflag_acquire(const int* p)
{
    int v;
    asm volatile("ld.acquire.cta.b32 %0, [%1];" : "=r"(v) : "l"(p) : "memory");
    return v;
}
__device__ __forceinline__ void sflag_release(int* p, int v)
{
    asm volatile("st.release.cta.b32 [%0], %1;" :: "l"(p), "r"(v) : "memory");
}

__global__ __launch_bounds__(NTHR, 1)
void dtw_mbox_kernel(const float* __restrict__ x,
                     const float* __restrict__ kern,
                     float* __restrict__ out)
{
    __shared__ __align__(16) float s_xring[4][64 * XSTRIDE]; // 20 KB x rings
    __shared__ __align__(16) float s_lbuf[2][CHUNK * R];     // 4 KB cross-CTA staging
    __shared__ __align__(16) float s_mslot[3][MBD][R];       // 1.5 KB mailboxes
    __shared__ int s_mflag[3];
    __shared__ int s_mcons[3];

    const int   c   = (int)blockIdx.x;
    const int   tid = (int)threadIdx.x;
    const int   w   = tid >> 5;
    const int   l   = tid & 31;
    const float INF = __int_as_float(0x7f800000);

    const float kv = kern[c * NTHR + tid];
    float* const myring = s_xring[w];

    if (tid < 3) { s_mflag[tid] = 0; s_mcons[tid] = 0; }

    // ---- initial x ring fill: ticks [-32w-31, -32w+32], 2 per lane ----
    #pragma unroll
    for (int k2 = 0; k2 < 2; ++k2) {
        const int T  = -32 * w - 31 + l + 32 * k2;
        const int Tc = min(max(T, 0), NTICK - 1);
        const float4* xp = (const float4*)(x + Tc * R);
        float4* dst = (float4*)&myring[(((unsigned)T) & 63u) * XSTRIDE];
        dst[0] = xp[0]; dst[1] = xp[1]; dst[2] = xp[2]; dst[3] = xp[3];
    }

    // ---- prestage cross-CTA chunk 0 (warp 0 only) ----
    if (c > 0 && w == 0) {
        if (l == 0) { while (gflag_acquire(&g_flag[c - 1]) < CHUNK) { } }
        __syncwarp();
        #pragma unroll
        for (int k2 = 0; k2 < 4; ++k2) {
            float4 v = __ldcg((const float4*)(g_edge[c - 1] + l * R) + k2);
            *(float4*)&s_lbuf[0][l * R + 4 * k2] = v;
        }
    }
    __syncthreads();   // one-time: flags + rings + staging visible to all warps

    float ev[R];
    #pragma unroll
    for (int r = 0; r < R; ++r) ev[r] = INF;
    float vprev = INF, dlast = INF;

    for (int i = 0; i < NITER; ++i) {
        // ---- left values from lane l-1 (previous tick's outputs) ----
        float L[R];
        #pragma unroll
        for (int r = 0; r < R; ++r)
            L[r] = __shfl_up_sync(0xffffffffu, ev[r], 1);

        // ---- every 32 iters: refill my x ring (+ warp-0 cross staging) ----
        if ((i & 31) == 0) {
            const int T  = i - 32 * w + l;             // ticks [i-32w, i-32w+31]
            const int Tc = min(max(T, 0), NTICK - 1);
            const float4* xp = (const float4*)(x + Tc * R);
            const float4 a = xp[0], b = xp[1], d2 = xp[2], e2 = xp[3];
            float4* dst = (float4*)&myring[(((unsigned)T) & 63u) * XSTRIDE];
            dst[0] = a; dst[1] = b; dst[2] = d2; dst[3] = e2;

            if (w == 0 && c > 0) {
                const int base = i + CHUNK;
                if (base < NTICK) {
                    if (l == 0) {
                        const int need = min(base + CHUNK, NTICK);   // FIX (a)
                        while (gflag_acquire(&g_flag[c - 1]) < need) { }
                    }
                    __syncwarp();
                    const int buf = ((i >> 5) + 1) & 1;
                    const int tk  = min(base + l, NTICK - 1);        // clamp OOB
                    #pragma unroll
                    for (int k2 = 0; k2 < 4; ++k2) {
                        float4 v = __ldcg((const float4*)(g_edge[c - 1] + tk * R) + k2);
                        *(float4*)&s_lbuf[buf][l * R + 4 * k2] = v;
                    }
                }
            }
            __syncwarp();   // refill visible before this iteration's consume
        }

        // ---- x for my 16 rows from the ring (conflict-free LDS) ----
        float xs[R];
        {
            const float4* sp = (const float4*)
                &myring[(((unsigned)(i - 32 * w - l)) & 63u) * XSTRIDE];
            const float4 a = sp[0], b = sp[1], d2 = sp[2], e2 = sp[3];
            xs[0]=a.x; xs[1]=a.y; xs[2]=a.z; xs[3]=a.w;
            xs[4]=b.x; xs[5]=b.y; xs[6]=b.z; xs[7]=b.w;
            xs[8]=d2.x; xs[9]=d2.y; xs[10]=d2.z; xs[11]=d2.w;
            xs[12]=e2.x; xs[13]=e2.y; xs[14]=e2.z; xs[15]=e2.w;
        }

        // ---- lane 0: boundary from staging buffer / mailbox ----
        if (l == 0) {
            const int t0 = i - 32 * w;
            float Lb[R];
            #pragma unroll
            for (int r = 0; r < R; ++r) Lb[r] = INF;
            if (w == 0) {
                if (c > 0) {
                    const float4* lp = (const float4*)&s_lbuf[(i >> 5) & 1][(i & 31) * R];
                    const float4 a = lp[0], b = lp[1], d2 = lp[2], e2 = lp[3];
                    Lb[0]=a.x; Lb[1]=a.y; Lb[2]=a.z; Lb[3]=a.w;
                    Lb[4]=b.x; Lb[5]=b.y; Lb[6]=b.z; Lb[7]=b.w;
                    Lb[8]=d2.x; Lb[9]=d2.y; Lb[10]=d2.z; Lb[11]=d2.w;
                    Lb[12]=e2.x; Lb[13]=e2.y; Lb[14]=e2.z; Lb[15]=e2.w;
                }
            } else {
                if (t0 >= 0 && t0 < NTICK) {                         // FIX (b)
                    while (sflag_acquire(&s_mflag[w - 1]) < i) { }
                    const float4* mp = (const float4*)s_mslot[w - 1][(i - 1) & (MBD - 1)];
                    const float4 a = mp[0], b = mp[1], d2 = mp[2], e2 = mp[3];
                    Lb[0]=a.x; Lb[1]=a.y; Lb[2]=a.z; Lb[3]=a.w;
                    Lb[4]=b.x; Lb[5]=b.y; Lb[6]=b.z; Lb[7]=b.w;
                    Lb[8]=d2.x; Lb[9]=d2.y; Lb[10]=d2.z; Lb[11]=d2.w;
                    Lb[12]=e2.x; Lb[13]=e2.y; Lb[14]=e2.z; Lb[15]=e2.w;
                }
                sflag_release(&s_mcons[w - 1], i + 1);  // progress (after read)
            }
            #pragma unroll
            for (int r = 0; r < R; ++r) L[r] = Lb[r];
            if (c == 0 && w == 0 && i == 0) L[0] = 0.0f;  // virtual 0 at (0,-1)
        }

        const int  t      = i - 32 * w - l;
        const bool active = (t >= 0) && (t < NTICK);

        // ---- m = min(diag, left) in place, then the serial fma chain ----
        const float lastL = L[R - 1];
        #pragma unroll
        for (int r = R - 1; r >= 1; --r)
            L[r] = fminf(L[r - 1], L[r]);
        L[0] = fminf(dlast, L[0]);

        float vp = vprev;
        #pragma unroll
        for (int r = 0; r < R; ++r) {
            const float tt = kv - xs[r];
            vp = fmaf(tt, tt, fminf(L[r], vp));
            ev[r] = vp;   // unconditional: inactive lanes feed inactive lanes
        }
        vprev = active ? vp : vprev;
        dlast = active ? lastL : dlast;

        // ---- publish right edge (lane 31) ----
        if (l == 31 && active) {
            const float4 a = make_float4(ev[0],  ev[1],  ev[2],  ev[3]);
            const float4 b = make_float4(ev[4],  ev[5],  ev[6],  ev[7]);
            const float4 d2 = make_float4(ev[8],  ev[9],  ev[10], ev[11]);
            const float4 e2 = make_float4(ev[12], ev[13], ev[14], ev[15]);
            if (w < 3) {
                while (sflag_acquire(&s_mcons[w]) < i - (MBD - 2)) { }  // backpressure
                float4* mp = (float4*)s_mslot[w][i & (MBD - 1)];
                mp[0] = a; mp[1] = b; mp[2] = d2; mp[3] = e2;
                sflag_release(&s_mflag[w], i + 1);
            } else if (c < NCTA - 1) {
                float4* ep = (float4*)(g_edge[c] + t * R);
                ep[0] = a; ep[1] = b; ep[2] = d2; ep[3] = e2;
                if ((t & 15) == 15)
                    gflag_release(&g_flag[c], t + 1);
            } else {
                float4* op = (float4*)(out + t * R);
                op[0] = a; op[1] = b; op[2] = d2; op[3] = e2;
            }
        }
    }
}

extern "C" void kernel_launch(void* const* d_in, const int* in_sizes, int n_in,
                              void* d_out, int out_size)
{
    const float* x = (const float*)d_in[0];   // input  [65536]
    const float* k = (const float*)d_in[1];   // kernel [512]
    float* out = (float*)d_out;               // [65536] float32

    dtw_init_flags<<<1, 32>>>();
    dtw_mbox_kernel<<<NCTA, NTHR>>>(x, k, out);
}

// round 8
// speedup vs baseline: 7.4846x; 7.4846x over previous
#include <cuda_runtime.h>

// DTW 65536 x 512 — 4 CTAs x 128 threads, 1 column/lane, R=16 rows/tick.
// ac[r][j] = min(ac[r-1][j-1], ac[r-1][j], ac[r][j-1]) + (k[j]-x[r])^2
// R8 = R5 (barrier-lockstep, measured best) with exactly one change:
// the per-lane x LDG prefetch (16 L1 lines per LDG.128) is replaced by
// per-warp smem rings refilled coalesced every 32 iterations and read with
// conflict-free LDS.128 (80B slot stride).

#define N_ROWS  65536
#define NCTA    4
#define NTHR    128
#define NWARP   4
#define R       16
#define NTICK   (N_ROWS / R)          // 4096
#define NITER   (NTICK + NTHR - 1)    // 4223
#define CHUNK   32                    // ticks per cross-CTA chunk
#define XSTRIDE 20                    // floats per ring slot (16 data + 4 pad)

__device__ __align__(16) float g_edge[NCTA - 1][N_ROWS];
__device__ int g_flag[NCTA - 1];

__global__ void dtw_init_flags()
{
    if (threadIdx.x < NCTA - 1) g_flag[threadIdx.x] = 0;
}

__device__ __forceinline__ int flag_acquire(const int* p)
{
    int v;
    asm volatile("ld.acquire.gpu.global.b32 %0, [%1];" : "=r"(v) : "l"(p) : "memory");
    return v;
}

__device__ __forceinline__ void flag_release(int* p, int v)
{
    asm volatile("st.release.gpu.global.b32 [%0], %1;" :: "l"(p), "r"(v) : "memory");
}

__global__ __launch_bounds__(NTHR, 1)
void dtw_pipe16r_kernel(const float* __restrict__ x,
                        const float* __restrict__ kern,
                        float* __restrict__ out)
{
    __shared__ __align__(16) float  s_xring[NWARP][64 * XSTRIDE]; // 20 KB x rings
    __shared__ __align__(16) float  lbuf[2][CHUNK * R];           // 4 KB cross-CTA staging
    __shared__ __align__(16) float4 edgebuf[2][NWARP][4];         // intra-CTA handoff

    const int   c   = (int)blockIdx.x;
    const int   tid = (int)threadIdx.x;
    const int   w   = tid >> 5;
    const int   l   = tid & 31;
    const float INF = __int_as_float(0x7f800000);

    const float kv    = kern[c * NTHR + tid];
    const bool  pred0 = (c == 0) && (tid == 0);
    float* const myring = s_xring[w];

    // ---- initial x ring fill: ticks [-32w-31, -32w+32], 2 slots per lane ----
    #pragma unroll
    for (int k2 = 0; k2 < 2; ++k2) {
        const int T  = -32 * w - 31 + l + 32 * k2;
        const int Tc = min(max(T, 0), NTICK - 1);
        const float4* xp = (const float4*)(x + Tc * R);
        float4* dst = (float4*)&myring[(((unsigned)T) & 63u) * XSTRIDE];
        dst[0] = xp[0]; dst[1] = xp[1]; dst[2] = xp[2]; dst[3] = xp[3];
    }

    // ---- prestage chunk 0 of the left-CTA boundary ----
    if (c == 0) {
        // CTA 0's left boundary is +INF everywhere (both buffers, never restaged)
        #pragma unroll
        for (int k = 0; k < (2 * CHUNK * R) / NTHR; ++k)
            lbuf[0][tid + NTHR * k] = INF;
    } else {
        if (tid == 0) {
            while (flag_acquire(&g_flag[c - 1]) < CHUNK) { }
        }
        __syncthreads();
        *(float4*)&lbuf[0][4 * tid] = __ldcg((const float4*)g_edge[c - 1] + tid);
    }
    __syncthreads();

    float ev[R];
    #pragma unroll
    for (int r = 0; r < R; ++r) ev[r] = INF;
    float vprev = INF, dlast = INF;

    for (int i = 0; i < NITER; ++i) {
        // ---- left-neighbor values (previous tick's ev of lane l-1) ----
        float L[R];
        #pragma unroll
        for (int r = 0; r < R; ++r)
            L[r] = __shfl_up_sync(0xffffffffu, ev[r], 1);

        // ---- every 32 iters: refill my ring + cross-CTA chunk staging ----
        if ((i & (CHUNK - 1)) == 0) {
            // x refill: ticks [i-32w, i-32w+31], one slot per lane, coalesced
            {
                const int T  = i - 32 * w + l;
                const int Tc = min(max(T, 0), NTICK - 1);
                const float4* xp = (const float4*)(x + Tc * R);
                const float4 a = xp[0], b = xp[1], d2 = xp[2], e2 = xp[3];
                float4* dst = (float4*)&myring[(((unsigned)T) & 63u) * XSTRIDE];
                dst[0] = a; dst[1] = b; dst[2] = d2; dst[3] = e2;
            }
            // boundary staging: ticks [i+32, i+64)
            if (c > 0) {
                const int base = i + CHUNK;
                if (base < NTICK) {
                    if (tid == 0) {
                        const int need = min(base + CHUNK, NTICK);
                        while (flag_acquire(&g_flag[c - 1]) < need) { }
                    }
                    __syncthreads();
                    const int buf = ((i >> 5) + 1) & 1;
                    *(float4*)&lbuf[buf][4 * tid] =
                        __ldcg((const float4*)(g_edge[c - 1] + base * R) + tid);
                    // consumed >= 32 iterations later; per-iteration barrier
                    // below orders these STS before those reads.
                }
            }
        }

        // ---- x for my 16 rows from the ring (conflict-free LDS.128) ----
        float xs[R];
        {
            const float4* sp = (const float4*)
                &myring[(((unsigned)(i - tid)) & 63u) * XSTRIDE];
            const float4 a = sp[0], b = sp[1], d2 = sp[2], e2 = sp[3];
            xs[0]=a.x;  xs[1]=a.y;  xs[2]=a.z;  xs[3]=a.w;
            xs[4]=b.x;  xs[5]=b.y;  xs[6]=b.z;  xs[7]=b.w;
            xs[8]=d2.x; xs[9]=d2.y; xs[10]=d2.z; xs[11]=d2.w;
            xs[12]=e2.x; xs[13]=e2.y; xs[14]=e2.z; xs[15]=e2.w;
        }

        // ---- lane-0 boundary source (warp-uniform branch, broadcast LDS) ----
        float4 e0, e1, e2, e3;
        if (w == 0) {
            const float4* lb = (const float4*)&lbuf[(i >> 5) & 1][(i & (CHUNK - 1)) * R];
            e0 = lb[0]; e1 = lb[1]; e2 = lb[2]; e3 = lb[3];
        } else {
            const float4* eb = (const float4*)edgebuf[(i & 1) ^ 1][w - 1];
            e0 = eb[0]; e1 = eb[1]; e2 = eb[2]; e3 = eb[3];
        }
        {
            const float Lb[R] = {e0.x, e0.y, e0.z, e0.w, e1.x, e1.y, e1.z, e1.w,
                                 e2.x, e2.y, e2.z, e2.w, e3.x, e3.y, e3.z, e3.w};
            #pragma unroll
            for (int r = 0; r < R; ++r)
                L[r] = (l == 0) ? Lb[r] : L[r];
        }
        // virtual 0 at (row 0, col -1): left-use only, at cell (0,0)
        L[0] = (pred0 && i == 0) ? 0.0f : L[0];

        const int  t      = i - tid;
        const bool active = (t >= 0) && (t < NTICK);

        // ---- m = min(diag, left), in place (descending keeps deps correct) ----
        const float lastL = L[R - 1];
        #pragma unroll
        for (int r = R - 1; r >= 1; --r)
            L[r] = fminf(L[r - 1], L[r]);
        L[0] = fminf(dlast, L[0]);

        // ---- off-chain residuals, then the 8-cyc/row serial chain ----
        float ts[R];
        #pragma unroll
        for (int r = 0; r < R; ++r) ts[r] = kv - xs[r];

        float vp = vprev;
        #pragma unroll
        for (int r = 0; r < R; ++r) {
            vp = fmaf(ts[r], ts[r], fminf(L[r], vp));
            ev[r] = vp;     // unconditional commit: inactive lanes' ev is
                            // only ever consumed by inactive neighbors
        }
        vprev = active ? vp : vprev;
        dlast = active ? lastL : dlast;

        // ---- publish right edge ----
        if (l == 31 && active) {
            const float4 a = make_float4(ev[0],  ev[1],  ev[2],  ev[3]);
            const float4 b = make_float4(ev[4],  ev[5],  ev[6],  ev[7]);
            const float4 d = make_float4(ev[8],  ev[9],  ev[10], ev[11]);
            const float4 e = make_float4(ev[12], ev[13], ev[14], ev[15]);
            if (w < NWARP - 1) {
                float4* eb = edgebuf[i & 1][w];
                eb[0] = a; eb[1] = b; eb[2] = d; eb[3] = e;
            } else if (c < NCTA - 1) {
                float4* ep = (float4*)(g_edge[c] + t * R);
                ep[0] = a; ep[1] = b; ep[2] = d; ep[3] = e;
                if ((t & 15) == 15)
                    flag_release(&g_flag[c], t + 1);
            } else {
                float4* op = (float4*)(out + t * R);
                op[0] = a; op[1] = b; op[2] = d; op[3] = e;
            }
        }

        __syncthreads();
    }
}

extern "C" void kernel_launch(void* const* d_in, const int* in_sizes, int n_in,
                              void* d_out, int out_size)
{
    const float* x = (const float*)d_in[0];   // input  [65536]
    const float* k = (const float*)d_in[1];   // kernel [512]
    float* out = (float*)d_out;               // [65536] float32

    dtw_init_flags<<<1, 32>>>();
    dtw_pipe16r_kernel<<<NCTA, NTHR>>>(x, k, out);
}

// round 9
// speedup vs baseline: 8.8547x; 1.1831x over previous
#include <cuda_runtime.h>

// DTW 65536 x 512 — 4 CTAs x 128 threads, 1 column/lane, R=32 rows/tick.
// ac[r][j] = min(ac[r-1][j-1], ac[r-1][j], ac[r][j-1]) + (k[j]-x[r])^2
// R9 = R8 with R=16 -> 32: halves the iteration count to amortize the
// ~430-cyc/iter fixed cost (shfl + barrier + branch machinery) measured
// across R5/R8. Everything else (barrier lockstep, per-warp smem x rings,
// edgebuf handoff, chunked cross-CTA staging) is unchanged in structure.

#define N_ROWS  65536
#define NCTA    4
#define NTHR    128
#define NWARP   4
#define R       32
#define NTICK   (N_ROWS / R)          // 2048
#define NITER   (NTICK + NTHR - 1)    // 2175
#define CHUNK   32                    // ticks per cross-CTA chunk
#define XSTRIDE 36                    // floats per ring slot (32 data + 4 pad)

__device__ __align__(16) float g_edge[NCTA - 1][N_ROWS];
__device__ int g_flag[NCTA - 1];

__global__ void dtw_init_flags()
{
    if (threadIdx.x < NCTA - 1) g_flag[threadIdx.x] = 0;
}

__device__ __forceinline__ int flag_acquire(const int* p)
{
    int v;
    asm volatile("ld.acquire.gpu.global.b32 %0, [%1];" : "=r"(v) : "l"(p) : "memory");
    return v;
}

__device__ __forceinline__ void flag_release(int* p, int v)
{
    asm volatile("st.release.gpu.global.b32 [%0], %1;" :: "l"(p), "r"(v) : "memory");
}

__global__ __launch_bounds__(NTHR, 1)
void dtw_pipe32_kernel(const float* __restrict__ x,
                       const float* __restrict__ kern,
                       float* __restrict__ out)
{
    __shared__ __align__(16) float  s_xring[NWARP][64 * XSTRIDE]; // 36 KB x rings
    __shared__ __align__(16) float  lbuf[2][CHUNK * R];           // 8 KB cross-CTA staging
    __shared__ __align__(16) float4 edgebuf[2][NWARP][8];         // intra-CTA handoff

    const int   c   = (int)blockIdx.x;
    const int   tid = (int)threadIdx.x;
    const int   w   = tid >> 5;
    const int   l   = tid & 31;
    const float INF = __int_as_float(0x7f800000);

    const float kv    = kern[c * NTHR + tid];
    const bool  pred0 = (c == 0) && (tid == 0);
    float* const myring = s_xring[w];

    // ---- initial x ring fill: ticks [-32w-31, -32w+32], 2 slots per lane ----
    #pragma unroll
    for (int k2 = 0; k2 < 2; ++k2) {
        const int T  = -32 * w - 31 + l + 32 * k2;
        const int Tc = min(max(T, 0), NTICK - 1);
        const float4* xp = (const float4*)(x + Tc * R);
        float4* dst = (float4*)&myring[(((unsigned)T) & 63u) * XSTRIDE];
        #pragma unroll
        for (int q = 0; q < 8; ++q) dst[q] = xp[q];
    }

    // ---- prestage chunk 0 of the left-CTA boundary ----
    if (c == 0) {
        #pragma unroll
        for (int k = 0; k < (2 * CHUNK * R) / NTHR; ++k)
            lbuf[0][tid + NTHR * k] = INF;
    } else {
        if (tid == 0) {
            while (flag_acquire(&g_flag[c - 1]) < CHUNK) { }
        }
        __syncthreads();
        #pragma unroll
        for (int k2 = 0; k2 < 2; ++k2)
            *(float4*)&lbuf[0][4 * (2 * tid + k2)] =
                __ldcg((const float4*)g_edge[c - 1] + 2 * tid + k2);
    }
    __syncthreads();

    float ev[R];
    #pragma unroll
    for (int r = 0; r < R; ++r) ev[r] = INF;
    float vprev = INF, dlast = INF;

    for (int i = 0; i < NITER; ++i) {
        // ---- left-neighbor values (previous tick's ev of lane l-1) ----
        float L[R];
        #pragma unroll
        for (int r = 0; r < R; ++r)
            L[r] = __shfl_up_sync(0xffffffffu, ev[r], 1);

        // ---- every 32 iters: refill my ring + cross-CTA chunk staging ----
        if ((i & (CHUNK - 1)) == 0) {
            {
                const int T  = i - 32 * w + l;
                const int Tc = min(max(T, 0), NTICK - 1);
                const float4* xp = (const float4*)(x + Tc * R);
                float4* dst = (float4*)&myring[(((unsigned)T) & 63u) * XSTRIDE];
                #pragma unroll
                for (int q = 0; q < 8; ++q) dst[q] = xp[q];
            }
            if (c > 0) {
                const int base = i + CHUNK;
                if (base < NTICK) {
                    if (tid == 0) {
                        const int need = min(base + CHUNK, NTICK);
                        while (flag_acquire(&g_flag[c - 1]) < need) { }
                    }
                    __syncthreads();
                    const int buf = ((i >> 5) + 1) & 1;
                    #pragma unroll
                    for (int k2 = 0; k2 < 2; ++k2)
                        *(float4*)&lbuf[buf][4 * (2 * tid + k2)] =
                            __ldcg((const float4*)(g_edge[c - 1] + base * R) + 2 * tid + k2);
                    // consumed >= 32 iterations later; per-iteration barrier
                    // below orders these STS before those reads.
                }
            }
        }

        // ---- lane-0 boundary source (warp-uniform branch, broadcast LDS) ----
        {
            float4 eb4[8];
            if (w == 0) {
                const float4* lb = (const float4*)&lbuf[(i >> 5) & 1][(i & (CHUNK - 1)) * R];
                #pragma unroll
                for (int q = 0; q < 8; ++q) eb4[q] = lb[q];
            } else {
                const float4* eb = (const float4*)edgebuf[(i & 1) ^ 1][w - 1];
                #pragma unroll
                for (int q = 0; q < 8; ++q) eb4[q] = eb[q];
            }
            const float* Lb = (const float*)eb4;
            #pragma unroll
            for (int r = 0; r < R; ++r)
                L[r] = (l == 0) ? Lb[r] : L[r];
        }
        // virtual 0 at (row 0, col -1): left-use only, at cell (0,0)
        L[0] = (pred0 && i == 0) ? 0.0f : L[0];

        const int  t      = i - tid;
        const bool active = (t >= 0) && (t < NTICK);

        // ---- m = min(diag, left), in place (descending keeps deps correct) ----
        const float lastL = L[R - 1];
        #pragma unroll
        for (int r = R - 1; r >= 1; --r)
            L[r] = fminf(L[r - 1], L[r]);
        L[0] = fminf(dlast, L[0]);

        // ---- x + serial chain, processed in two halves of 16 rows ----
        const float* sp = &myring[(((unsigned)(i - tid)) & 63u) * XSTRIDE];
        float vp = vprev;
        #pragma unroll
        for (int h = 0; h < 2; ++h) {
            float xs[16];
            {
                const float4* s4 = (const float4*)(sp + 16 * h);
                const float4 a = s4[0], b = s4[1], d2 = s4[2], e2 = s4[3];
                xs[0]=a.x;  xs[1]=a.y;  xs[2]=a.z;  xs[3]=a.w;
                xs[4]=b.x;  xs[5]=b.y;  xs[6]=b.z;  xs[7]=b.w;
                xs[8]=d2.x; xs[9]=d2.y; xs[10]=d2.z; xs[11]=d2.w;
                xs[12]=e2.x; xs[13]=e2.y; xs[14]=e2.z; xs[15]=e2.w;
            }
            #pragma unroll
            for (int r = 0; r < 16; ++r) {
                const float tt = kv - xs[r];
                vp = fmaf(tt, tt, fminf(L[16 * h + r], vp));
                ev[16 * h + r] = vp;   // unconditional: inactive lanes' ev is
                                       // only ever consumed by inactive lanes
            }
        }
        vprev = active ? vp : vprev;
        dlast = active ? lastL : dlast;

        // ---- publish right edge ----
        if (l == 31 && active) {
            float4 o4[8];
            #pragma unroll
            for (int q = 0; q < 8; ++q)
                o4[q] = make_float4(ev[4*q], ev[4*q+1], ev[4*q+2], ev[4*q+3]);
            if (w < NWARP - 1) {
                float4* eb = edgebuf[i & 1][w];
                #pragma unroll
                for (int q = 0; q < 8; ++q) eb[q] = o4[q];
            } else if (c < NCTA - 1) {
                float4* ep = (float4*)(g_edge[c] + t * R);
                #pragma unroll
                for (int q = 0; q < 8; ++q) ep[q] = o4[q];
                if ((t & 7) == 7)
                    flag_release(&g_flag[c], t + 1);
            } else {
                float4* op = (float4*)(out + t * R);
                #pragma unroll
                for (int q = 0; q < 8; ++q) op[q] = o4[q];
            }
        }

        __syncthreads();
    }
}

extern "C" void kernel_launch(void* const* d_in, const int* in_sizes, int n_in,
                              void* d_out, int out_size)
{
    const float* x = (const float*)d_in[0];   // input  [65536]
    const float* k = (const float*)d_in[1];   // kernel [512]
    float* out = (float*)d_out;               // [65536] float32

    dtw_init_flags<<<1, 32>>>();
    dtw_pipe32_kernel<<<NCTA, NTHR>>>(x, k, out);
}

// round 10
// speedup vs baseline: 9.2357x; 1.0430x over previous
#include <cuda_runtime.h>

// DTW 65536 x 512 — 4 CTAs x 128 threads, 1 column/lane, R=32 rows/tick.
// ac[r][j] = min(ac[r-1][j-1], ac[r-1][j], ac[r][j-1]) + (k[j]-x[r])^2
// R10 = R9 with the per-tick serial min-add chain (8 cyc/row) replaced by the
// min-plus prefix decomposition (the reference's own cumsum+cummin trick,
// applied along rows within a lane):
//   S[r]  = running sum of d[r]          (serial FFMA chain, 4 cyc/step)
//   cm[r] = min(cm[r-1], m[r] - S[r-1])  (serial FMNMX chain, 4 cyc/step)
//   ev[r] = S[r] + cm[r]                 (off-chain FADD)
// The two 4-cyc chains run concurrently -> in-tick critical path 256 -> ~140.

#define N_ROWS  65536
#define NCTA    4
#define NTHR    128
#define NWARP   4
#define R       32
#define NTICK   (N_ROWS / R)          // 2048
#define NITER   (NTICK + NTHR - 1)    // 2175
#define CHUNK   32                    // ticks per cross-CTA chunk
#define XSTRIDE 36                    // floats per ring slot (32 data + 4 pad)

__device__ __align__(16) float g_edge[NCTA - 1][N_ROWS];
__device__ int g_flag[NCTA - 1];

__global__ void dtw_init_flags()
{
    if (threadIdx.x < NCTA - 1) g_flag[threadIdx.x] = 0;
}

__device__ __forceinline__ int flag_acquire(const int* p)
{
    int v;
    asm volatile("ld.acquire.gpu.global.b32 %0, [%1];" : "=r"(v) : "l"(p) : "memory");
    return v;
}

__device__ __forceinline__ void flag_release(int* p, int v)
{
    asm volatile("st.release.gpu.global.b32 [%0], %1;" :: "l"(p), "r"(v) : "memory");
}

__global__ __launch_bounds__(NTHR, 1)
void dtw_prefix_kernel(const float* __restrict__ x,
                       const float* __restrict__ kern,
                       float* __restrict__ out)
{
    __shared__ __align__(16) float  s_xring[NWARP][64 * XSTRIDE]; // 36 KB x rings
    __shared__ __align__(16) float  lbuf[2][CHUNK * R];           // 8 KB cross-CTA staging
    __shared__ __align__(16) float4 edgebuf[2][NWARP][8];         // intra-CTA handoff

    const int   c   = (int)blockIdx.x;
    const int   tid = (int)threadIdx.x;
    const int   w   = tid >> 5;
    const int   l   = tid & 31;
    const float INF = __int_as_float(0x7f800000);

    const float kv    = kern[c * NTHR + tid];
    const bool  pred0 = (c == 0) && (tid == 0);
    float* const myring = s_xring[w];

    // ---- initial x ring fill: ticks [-32w-31, -32w+32], 2 slots per lane ----
    #pragma unroll
    for (int k2 = 0; k2 < 2; ++k2) {
        const int T  = -32 * w - 31 + l + 32 * k2;
        const int Tc = min(max(T, 0), NTICK - 1);
        const float4* xp = (const float4*)(x + Tc * R);
        float4* dst = (float4*)&myring[(((unsigned)T) & 63u) * XSTRIDE];
        #pragma unroll
        for (int q = 0; q < 8; ++q) dst[q] = xp[q];
    }

    // ---- prestage chunk 0 of the left-CTA boundary ----
    if (c == 0) {
        #pragma unroll
        for (int k = 0; k < (2 * CHUNK * R) / NTHR; ++k)
            lbuf[0][tid + NTHR * k] = INF;
    } else {
        if (tid == 0) {
            while (flag_acquire(&g_flag[c - 1]) < CHUNK) { }
        }
        __syncthreads();
        #pragma unroll
        for (int k2 = 0; k2 < 2; ++k2)
            *(float4*)&lbuf[0][4 * (2 * tid + k2)] =
                __ldcg((const float4*)g_edge[c - 1] + 2 * tid + k2);
    }
    __syncthreads();

    float ev[R];
    #pragma unroll
    for (int r = 0; r < R; ++r) ev[r] = INF;
    float vprev = INF, dlast = INF;

    for (int i = 0; i < NITER; ++i) {
        // ---- left-neighbor values (previous tick's ev of lane l-1) ----
        float L[R];
        #pragma unroll
        for (int r = 0; r < R; ++r)
            L[r] = __shfl_up_sync(0xffffffffu, ev[r], 1);

        // ---- every 32 iters: refill my ring + cross-CTA chunk staging ----
        if ((i & (CHUNK - 1)) == 0) {
            {
                const int T  = i - 32 * w + l;
                const int Tc = min(max(T, 0), NTICK - 1);
                const float4* xp = (const float4*)(x + Tc * R);
                float4* dst = (float4*)&myring[(((unsigned)T) & 63u) * XSTRIDE];
                #pragma unroll
                for (int q = 0; q < 8; ++q) dst[q] = xp[q];
            }
            if (c > 0) {
                const int base = i + CHUNK;
                if (base < NTICK) {
                    if (tid == 0) {
                        const int need = min(base + CHUNK, NTICK);
                        while (flag_acquire(&g_flag[c - 1]) < need) { }
                    }
                    __syncthreads();
                    const int buf = ((i >> 5) + 1) & 1;
                    #pragma unroll
                    for (int k2 = 0; k2 < 2; ++k2)
                        *(float4*)&lbuf[buf][4 * (2 * tid + k2)] =
                            __ldcg((const float4*)(g_edge[c - 1] + base * R) + 2 * tid + k2);
                    // consumed >= 32 iterations later; per-iteration barrier
                    // below orders these STS before those reads.
                }
            }
        }

        // ---- lane-0 boundary source (warp-uniform branch, broadcast LDS) ----
        {
            float4 eb4[8];
            if (w == 0) {
                const float4* lb = (const float4*)&lbuf[(i >> 5) & 1][(i & (CHUNK - 1)) * R];
                #pragma unroll
                for (int q = 0; q < 8; ++q) eb4[q] = lb[q];
            } else {
                const float4* eb = (const float4*)edgebuf[(i & 1) ^ 1][w - 1];
                #pragma unroll
                for (int q = 0; q < 8; ++q) eb4[q] = eb[q];
            }
            const float* Lb = (const float*)eb4;
            #pragma unroll
            for (int r = 0; r < R; ++r)
                L[r] = (l == 0) ? Lb[r] : L[r];
        }
        // virtual 0 at (row 0, col -1): left-use only, at cell (0,0)
        L[0] = (pred0 && i == 0) ? 0.0f : L[0];

        const int  t      = i - tid;
        const bool active = (t >= 0) && (t < NTICK);

        // ---- m = min(diag, left), in place (descending keeps deps correct) ----
        const float lastL = L[R - 1];
        #pragma unroll
        for (int r = R - 1; r >= 1; --r)
            L[r] = fminf(L[r - 1], L[r]);
        L[0] = fminf(dlast, L[0]);

        // ---- x residuals (parallel, off-chain) ----
        float ts[R];
        {
            const float* sp = &myring[(((unsigned)(i - tid)) & 63u) * XSTRIDE];
            #pragma unroll
            for (int h = 0; h < 8; ++h) {
                const float4 a = ((const float4*)sp)[h];
                ts[4*h]   = kv - a.x;
                ts[4*h+1] = kv - a.y;
                ts[4*h+2] = kv - a.z;
                ts[4*h+3] = kv - a.w;
            }
        }

        // ---- min-plus prefix: two concurrent 4-cyc chains ----
        // S  = running sum of d[r] (FFMA chain)
        // cm = running min of (m[r] - S[r-1]) seeded with min(vprev, m[0])
        // ev[r] = S[r] + cm[r]  (off the critical chain)
        float S  = ts[0] * ts[0];
        float cm = fminf(vprev, L[0]);
        ev[0] = S + cm;
        #pragma unroll
        for (int r = 1; r < R; ++r) {
            const float q = L[r] - S;           // m[r] - S[r-1]
            S  = fmaf(ts[r], ts[r], S);         // S[r]
            cm = fminf(cm, q);                  // cm[r]
            ev[r] = S + cm;                     // unconditional commit
        }
        vprev = active ? ev[R - 1] : vprev;
        dlast = active ? lastL : dlast;

        // ---- publish right edge ----
        if (l == 31 && active) {
            float4 o4[8];
            #pragma unroll
            for (int q = 0; q < 8; ++q)
                o4[q] = make_float4(ev[4*q], ev[4*q+1], ev[4*q+2], ev[4*q+3]);
            if (w < NWARP - 1) {
                float4* eb = edgebuf[i & 1][w];
                #pragma unroll
                for (int q = 0; q < 8; ++q) eb[q] = o4[q];
            } else if (c < NCTA - 1) {
                float4* ep = (float4*)(g_edge[c] + t * R);
                #pragma unroll
                for (int q = 0; q < 8; ++q) ep[q] = o4[q];
                if ((t & 7) == 7)
                    flag_release(&g_flag[c], t + 1);
            } else {
                float4* op = (float4*)(out + t * R);
                #pragma unroll
                for (int q = 0; q < 8; ++q) op[q] = o4[q];
            }
        }

        __syncthreads();
    }
}

extern "C" void kernel_launch(void* const* d_in, const int* in_sizes, int n_in,
                              void* d_out, int out_size)
{
    const float* x = (const float*)d_in[0];   // input  [65536]
    const float* k = (const float*)d_in[1];   // kernel [512]
    float* out = (float*)d_out;               // [65536] float32

    dtw_init_flags<<<1, 32>>>();
    dtw_prefix_kernel<<<NCTA, NTHR>>>(x, k, out);
}